// round 4
// baseline (speedup 1.0000x reference)
#include <cuda_runtime.h>
#include <cstdint>

typedef unsigned long long ull;

#define PP   64
#define HH   256
#define BB   32
#define TT   128
#define LE   10
#define LD   118
#define K3H  768   // 3*H
#define PADU 18    // padded smem row width in ull (16 data + 2 pad), keeps 16B align

#define PRED_ELEMS (PP * BB * LD)
#define MU_OFF     PRED_ELEMS
#define LV_OFF     (PRED_ELEMS + BB * HH)

// ---- scratch (static device allocations) ----------------------------------
// +4*K3H pad: prefetch pipeline reads one 4-layer block past each section end.
__device__ float g_Wt_hh[PP * HH * K3H + 4 * K3H];   // [p][h][k]
__device__ float g_Wt_ih[PP * PP * K3H + 4 * K3H];   // [p][i][k]
__device__ float g_Xt[LD * PP * BB];                 // [l][i][b]
__device__ float g_xpe[LE * BB * K3H];               // [l][b][k]
__device__ float g_hT[BB * HH];
__device__ float g_z[BB * HH];

// ---- helpers --------------------------------------------------------------
__device__ __forceinline__ ull fma2(ull a, ull b, ull c) {
    ull d;
    asm("fma.rn.f32x2 %0, %1, %2, %3;" : "=l"(d) : "l"(a), "l"(b), "l"(c));
    return d;
}
__device__ __forceinline__ ull bcast2(float x) {
    ull d;
    asm("mov.b64 %0, {%1, %1};" : "=l"(d) : "f"(x));
    return d;
}
__device__ __forceinline__ void unpack2(ull v, float& x, float& y) {
    asm("mov.b64 {%0, %1}, %2;" : "=f"(x), "=f"(y) : "l"(v));
}
__device__ __forceinline__ float sigf(float x) {
    return __fdividef(1.0f, 1.0f + __expf(-x));
}
__device__ __forceinline__ float tfast(float x) {
    float e = __expf(2.0f * x);
    return 1.0f - __fdividef(2.0f, e + 1.0f);
}

// ---- K1: transpose Whh_d [p][k][h] -> g_Wt_hh [p][h][k] -------------------
__global__ void transpose_hh_kernel(const float* __restrict__ in) {
    __shared__ float tile[32][33];
    const int rows = K3H, cols = HH;
    const float* ip = in + (size_t)blockIdx.z * rows * cols;
    float* op = g_Wt_hh + (size_t)blockIdx.z * rows * cols;
    int c0 = blockIdx.x * 32, r0 = blockIdx.y * 32;
    int tx = threadIdx.x, ty = threadIdx.y;
#pragma unroll
    for (int dy = 0; dy < 32; dy += 8)
        tile[ty + dy][tx] = ip[(r0 + ty + dy) * cols + (c0 + tx)];
    __syncthreads();
#pragma unroll
    for (int dy = 0; dy < 32; dy += 8)
        op[(c0 + ty + dy) * rows + (r0 + tx)] = tile[tx][ty + dy];
}

// ---- K2: transpose Wih_d [p][k][i] -> g_Wt_ih [p][i][k] -------------------
__global__ void transpose_ih_kernel(const float* __restrict__ in) {
    __shared__ float tile[32][33];
    const int rows = K3H, cols = PP;
    const float* ip = in + (size_t)blockIdx.z * rows * cols;
    float* op = g_Wt_ih + (size_t)blockIdx.z * rows * cols;
    int c0 = blockIdx.x * 32, r0 = blockIdx.y * 32;
    int tx = threadIdx.x, ty = threadIdx.y;
#pragma unroll
    for (int dy = 0; dy < 32; dy += 8)
        tile[ty + dy][tx] = ip[(r0 + ty + dy) * cols + (c0 + tx)];
    __syncthreads();
#pragma unroll
    for (int dy = 0; dy < 32; dy += 8)
        op[(c0 + ty + dy) * rows + (r0 + tx)] = tile[tx][ty + dy];
}

// ---- K3: Xt[l][i][b] = (l==0 ? 0 : X[b][l+9][i]) --------------------------
__global__ void build_xt_kernel(const float* __restrict__ X) {
    int idx = blockIdx.x * blockDim.x + threadIdx.x;
    if (idx >= LD * PP * BB) return;
    int b = idx & 31;
    int r = idx >> 5;
    int i = r & 63;
    int l = r >> 6;
    g_Xt[idx] = (l == 0) ? 0.0f : X[b * (TT * PP) + (l + 9) * PP + i];
}

// ---- K4: encoder input projection -----------------------------------------
__global__ void xpe_kernel(const float* __restrict__ X,
                           const float* __restrict__ Wih_e,
                           const float* __restrict__ bih_e) {
    __shared__ float xr[PP];
    int b = blockIdx.x, l = blockIdx.y;
    int tid = threadIdx.x;  // 256
    if (tid < PP) xr[tid] = X[b * (TT * PP) + l * PP + tid];
    __syncthreads();
#pragma unroll
    for (int g = 0; g < 3; ++g) {
        int k = g * HH + tid;
        float a = bih_e[k];
        const float* w = Wih_e + k * PP;
#pragma unroll
        for (int i = 0; i < PP; i += 4) {
            float4 wv = *(const float4*)(w + i);
            a += wv.x * xr[i] + wv.y * xr[i + 1] + wv.z * xr[i + 2] + wv.w * xr[i + 3];
        }
        g_xpe[(l * BB + b) * K3H + k] = a;
    }
}

// ---- K5: encoder GRU scan -------------------------------------------------
__global__ void enc_kernel(const float* __restrict__ Whh_e,
                           const float* __restrict__ bhh_e) {
    __shared__ float hs[HH];
    int b = blockIdx.x, j = threadIdx.x;
    hs[j] = 0.0f;
    float bR = bhh_e[j], bZ = bhh_e[HH + j], bN = bhh_e[2 * HH + j];
    const float* wR = Whh_e + j * HH;
    const float* wZ = Whh_e + (HH + j) * HH;
    const float* wN = Whh_e + (2 * HH + j) * HH;
    __syncthreads();
    for (int l = 0; l < LE; ++l) {
        float aR = 0.f, aZ = 0.f, aN = 0.f;
#pragma unroll 8
        for (int h = 0; h < HH; h += 4) {
            float4 hv = *(const float4*)&hs[h];
            float4 r4 = *(const float4*)(wR + h);
            float4 z4 = *(const float4*)(wZ + h);
            float4 n4 = *(const float4*)(wN + h);
            aR += r4.x * hv.x + r4.y * hv.y + r4.z * hv.z + r4.w * hv.w;
            aZ += z4.x * hv.x + z4.y * hv.y + z4.z * hv.z + z4.w * hv.w;
            aN += n4.x * hv.x + n4.y * hv.y + n4.z * hv.z + n4.w * hv.w;
        }
        const float* xp = g_xpe + (l * BB + b) * K3H;
        float r = sigf(xp[j] + aR + bR);
        float z = sigf(xp[HH + j] + aZ + bZ);
        float n = tfast(xp[2 * HH + j] + r * (aN + bN));
        float hold = hs[j];
        __syncthreads();
        hs[j] = (1.0f - z) * n + z * hold;
        __syncthreads();
    }
    g_hT[b * HH + j] = hs[j];
}

// ---- K6: mu / log_var / z -------------------------------------------------
__global__ void muz_kernel(const float* __restrict__ Wmu,
                           const float* __restrict__ bmu,
                           const float* __restrict__ Wstd,
                           const float* __restrict__ bstd,
                           const float* __restrict__ eps,
                           float* __restrict__ out) {
    __shared__ float hs[HH];
    int b = blockIdx.x, j = threadIdx.x;
    hs[j] = g_hT[b * HH + j];
    __syncthreads();
    float am = bmu[j], as = bstd[j];
    const float* wm = Wmu + j * HH;
    const float* ws = Wstd + j * HH;
#pragma unroll 8
    for (int h = 0; h < HH; h += 4) {
        float4 hv = *(const float4*)&hs[h];
        float4 m4 = *(const float4*)(wm + h);
        float4 s4 = *(const float4*)(ws + h);
        am += m4.x * hv.x + m4.y * hv.y + m4.z * hv.z + m4.w * hv.w;
        as += s4.x * hv.x + s4.y * hv.y + s4.z * hv.z + s4.w * hv.w;
    }
    out[MU_OFF + b * HH + j] = am;
    out[LV_OFF + b * HH + j] = as;
    g_z[b * HH + j] = am + expf(0.5f * as) * eps[b * HH + j];
}

// ---- decoder inner-loop building blocks -----------------------------------
__device__ __forceinline__ void loadW(ull (&w)[12], const float* base) {
#pragma unroll
    for (int l = 0; l < 4; ++l) {
        const float* r = base + l * K3H;
        w[l * 3 + 0] = *(const ull*)(r);
        w[l * 3 + 1] = *(const ull*)(r + HH);
        w[l * 3 + 2] = *(const ull*)(r + 2 * HH);
    }
}

// src holds operands pre-duplicated as f32x2 (ull per (row, b)).
// All lanes of a warp read the same address -> smem broadcast (free).
__device__ __forceinline__ void comp4(const ull (&w)[12],
                                      const ull (*src)[PADU], int r0, int bc,
                                      ull (&aR)[8], ull (&aZ)[8], ull (&aN)[8]) {
#pragma unroll
    for (int l = 0; l < 4; ++l) {
        const ull* row = &src[r0 + l][bc];
        ulonglong2 p0 = *(const ulonglong2*)(row);
        ulonglong2 p1 = *(const ulonglong2*)(row + 2);
        ulonglong2 p2 = *(const ulonglong2*)(row + 4);
        ulonglong2 p3 = *(const ulonglong2*)(row + 6);
        ull hv[8] = {p0.x, p0.y, p1.x, p1.y, p2.x, p2.y, p3.x, p3.y};
#pragma unroll
        for (int b = 0; b < 8; ++b) {
            aR[b] = fma2(hv[b], w[l * 3 + 0], aR[b]);
            aZ[b] = fma2(hv[b], w[l * 3 + 1], aZ[b]);
            aN[b] = fma2(hv[b], w[l * 3 + 2], aN[b]);
        }
    }
}

// ---- K7: decoder scan -----------------------------------------------------
// 128 CTAs = 64 p x 2 b-halves (16 b).  256 threads = 2 bg (8 b) x 128 jg (2 j).
// h and x live in smem as pre-duplicated f32x2 -> zero broadcast MOVs in the
// inner loop.  Weights double-buffered in registers (4-layer blocks, 384-cyc
// prefetch distance >> 262-cyc L2 latency).
__global__ __launch_bounds__(256, 1) void dec_kernel(
    const float* __restrict__ bih_d, const float* __restrict__ bhh_d,
    const float* __restrict__ Wlin, const float* __restrict__ blin,
    float* __restrict__ out) {
    __shared__ ull h_d[HH][PADU];   // 36.9 KB, duplicated h
    __shared__ ull x_d[PP][PADU];   //  9.2 KB, duplicated x
    __shared__ float red_s[8][8];

    const int tid = threadIdx.x;
    const int p  = blockIdx.x >> 1;
    const int b0 = (blockIdx.x & 1) * 16;
    const int bg = tid >> 7;          // 0..1
    const int jg = tid & 127;         // 0..127
    const int j0 = jg * 2;
    const int bc = bg * 8;
    const int lane = tid & 31, warp = tid >> 5;

    const float* WtH = g_Wt_hh + (size_t)p * HH * K3H + j0;
    const float* WtI = g_Wt_ih + (size_t)p * PP * K3H + j0;

    for (int idx = tid; idx < HH * 16; idx += 256) {
        int bb = idx & 15, j = idx >> 4;
        h_d[j][bb] = bcast2(g_z[(b0 + bb) * HH + j]);
    }
    const float bR0  = bih_d[p * K3H + j0]          + bhh_d[p * K3H + j0];
    const float bR1  = bih_d[p * K3H + j0 + 1]      + bhh_d[p * K3H + j0 + 1];
    const float bZ0  = bih_d[p * K3H + HH + j0]     + bhh_d[p * K3H + HH + j0];
    const float bZ1  = bih_d[p * K3H + HH + j0 + 1] + bhh_d[p * K3H + HH + j0 + 1];
    const float bNx0 = bih_d[p * K3H + 2 * HH + j0];
    const float bNx1 = bih_d[p * K3H + 2 * HH + j0 + 1];
    const float bNh0 = bhh_d[p * K3H + 2 * HH + j0];
    const float bNh1 = bhh_d[p * K3H + 2 * HH + j0 + 1];
    const float blin_p = blin[p];
    const float wl0 = Wlin[p * HH + j0];
    const float wl1 = Wlin[p * HH + j0 + 1];

#pragma unroll 1
    for (int l = 0; l < LD; ++l) {
        __syncthreads();   // prev-step h_d writes + red_s reuse
        {   // stage x (duplicated) for this step
            int i = tid >> 2, q = tid & 3;
            float4 v = *(const float4*)&g_Xt[l * (PP * BB) + i * BB + b0 + q * 4];
            ulonglong2 d0 = make_ulonglong2(bcast2(v.x), bcast2(v.y));
            ulonglong2 d1 = make_ulonglong2(bcast2(v.z), bcast2(v.w));
            *(ulonglong2*)&x_d[i][q * 4]     = d0;
            *(ulonglong2*)&x_d[i][q * 4 + 2] = d1;
        }
        __syncthreads();

        ull aR[8], aZ[8], aNx[8], aNh[8];
#pragma unroll
        for (int b = 0; b < 8; ++b) { aR[b] = 0; aZ[b] = 0; aNx[b] = 0; aNh[b] = 0; }

        ull wa[12], wb[12];
        // ---- input projection: 64 i-layers, 16 blocks, double buffered ----
        loadW(wa, WtI);
#pragma unroll 1
        for (int ib = 0; ib < 16; ib += 2) {
            loadW(wb, WtI + (ib + 1) * (4 * K3H));
            comp4(wa, x_d, ib * 4, bc, aR, aZ, aNx);
            loadW(wa, WtI + (ib + 2) * (4 * K3H));   // last iter reads pad: harmless
            comp4(wb, x_d, ib * 4 + 4, bc, aR, aZ, aNx);
        }
        // ---- recurrent: 256 h-layers, 64 blocks, double buffered ----------
        loadW(wa, WtH);
#pragma unroll 1
        for (int hb = 0; hb < 64; hb += 2) {
            loadW(wb, WtH + (hb + 1) * (4 * K3H));
            comp4(wa, h_d, hb * 4, bc, aR, aZ, aNh);
            loadW(wa, WtH + (hb + 2) * (4 * K3H));   // last iter reads pad: harmless
            comp4(wb, h_d, hb * 4 + 4, bc, aR, aZ, aNh);
        }
        __syncthreads();   // all GEMM reads of h_d complete

        // ---- gate epilogue + h update + linear-head partials --------------
        float h0v[8], h1v[8];
#pragma unroll
        for (int b = 0; b < 8; ++b) {
            float lo, hi;
            unpack2(h_d[j0][bc + b], lo, hi);     (void)hi;
            h0v[b] = lo;
            unpack2(h_d[j0 + 1][bc + b], lo, hi); (void)hi;
            h1v[b] = lo;
        }

        float hn0[8], hn1[8], part[8];
#pragma unroll
        for (int b = 0; b < 8; ++b) {
            float r0v, r1v, z0v, z1v, nx0, nx1, nh0, nh1;
            unpack2(aR[b], r0v, r1v);
            unpack2(aZ[b], z0v, z1v);
            unpack2(aNx[b], nx0, nx1);
            unpack2(aNh[b], nh0, nh1);
            float rg0 = sigf(r0v + bR0);
            float rg1 = sigf(r1v + bR1);
            float zg0 = sigf(z0v + bZ0);
            float zg1 = sigf(z1v + bZ1);
            float n0 = tfast(nx0 + bNx0 + rg0 * (nh0 + bNh0));
            float n1 = tfast(nx1 + bNx1 + rg1 * (nh1 + bNh1));
            float a0 = n0 + zg0 * (h0v[b] - n0);
            float a1 = n1 + zg1 * (h1v[b] - n1);
            hn0[b] = a0; hn1[b] = a1;
            part[b] = a0 * wl0 + a1 * wl1;
        }
        // write duplicated new h
#pragma unroll
        for (int q = 0; q < 4; ++q) {
            *(ulonglong2*)&h_d[j0][bc + q * 2] =
                make_ulonglong2(bcast2(hn0[q * 2]), bcast2(hn0[q * 2 + 1]));
            *(ulonglong2*)&h_d[j0 + 1][bc + q * 2] =
                make_ulonglong2(bcast2(hn1[q * 2]), bcast2(hn1[q * 2 + 1]));
        }

#pragma unroll
        for (int off = 16; off; off >>= 1)
#pragma unroll
            for (int b = 0; b < 8; ++b)
                part[b] += __shfl_down_sync(0xffffffffu, part[b], off);
        if (lane == 0) {
#pragma unroll
            for (int b = 0; b < 8; ++b) red_s[warp][b] = part[b];
        }
        __syncthreads();
        if (tid < 16) {
            int bgq = tid >> 3, ib = tid & 7;
            float s = red_s[bgq * 4][ib] + red_s[bgq * 4 + 1][ib] +
                      red_s[bgq * 4 + 2][ib] + red_s[bgq * 4 + 3][ib] + blin_p;
            out[(p * BB + b0 + bgq * 8 + ib) * LD + l] = s;
        }
    }
}

// ---------------------------------------------------------------------------
extern "C" void kernel_launch(void* const* d_in, const int* in_sizes, int n_in,
                              void* d_out, int out_size) {
    const float* X     = (const float*)d_in[0];
    const float* eps   = (const float*)d_in[1];
    // d_in[2] = connection (all-ones -> gather identity; unused)
    const float* Wih_e = (const float*)d_in[3];
    const float* Whh_e = (const float*)d_in[4];
    const float* bih_e = (const float*)d_in[5];
    const float* bhh_e = (const float*)d_in[6];
    const float* Wmu   = (const float*)d_in[7];
    const float* bmu   = (const float*)d_in[8];
    const float* Wstd  = (const float*)d_in[9];
    const float* bstd  = (const float*)d_in[10];
    const float* Wih_d = (const float*)d_in[11];
    const float* Whh_d = (const float*)d_in[12];
    const float* bih_d = (const float*)d_in[13];
    const float* bhh_d = (const float*)d_in[14];
    const float* Wlin  = (const float*)d_in[15];
    const float* blin  = (const float*)d_in[16];
    float* out = (float*)d_out;

    transpose_hh_kernel<<<dim3(HH / 32, K3H / 32, PP), dim3(32, 8)>>>(Whh_d);
    transpose_ih_kernel<<<dim3(PP / 32, K3H / 32, PP), dim3(32, 8)>>>(Wih_d);
    build_xt_kernel<<<(LD * PP * BB + 255) / 256, 256>>>(X);
    xpe_kernel<<<dim3(BB, LE), 256>>>(X, Wih_e, bih_e);
    enc_kernel<<<BB, 256>>>(Whh_e, bhh_e);
    muz_kernel<<<BB, 256>>>(Wmu, bmu, Wstd, bstd, eps, out);
    dec_kernel<<<128, 256>>>(bih_d, bhh_d, Wlin, blin, out);
}